// round 3
// baseline (speedup 1.0000x reference)
#include <cuda_runtime.h>
#include <cstdint>

// FConvLayer: irfft(rfft(x)*rfft(w_pad)) ortho == circular depthwise conv / 64.
// y[b,t,h] = (1/64) * sum_{k<16} w[k,h] * x[b,(t-k) mod 4096,h]
// out = LayerNorm_H(y + x) * ln_w + ln_b
//
// R2 design: SCATTER-form register conv (no history ring).
//  - 1 warp = 128-row t-strip; lane l owns h in [4l,4l+4) as two f32x2 pairs.
//  - 16 forward partial accumulators: input row t adds w[k]*x[t] to acc[(t+k)&15].
//    Output row t completes when row t is consumed -> residual x[t] is the live
//    register, no history storage needed.
//  - k=15 contribution OVERWRITES its slot (implicit accumulator reset).
//  - 4-deep global prefetch queue; packed fma.rn.f32x2 throughout.
//  - Register budget ~165 -> 3 CTAs/SM (12 warps) via __launch_bounds__(128,3).

typedef unsigned long long u64;
#define DINL __device__ __forceinline__

DINL u64 pack2(float lo, float hi) {
    u64 r; asm("mov.b64 %0, {%1,%2};" : "=l"(r) : "f"(lo), "f"(hi)); return r;
}
DINL void unpack2(u64 v, float& lo, float& hi) {
    asm("mov.b64 {%0,%1}, %2;" : "=f"(lo), "=f"(hi) : "l"(v));
}
DINL u64 fma2(u64 a, u64 b, u64 c) {
    u64 d; asm("fma.rn.f32x2 %0,%1,%2,%3;" : "=l"(d) : "l"(a), "l"(b), "l"(c)); return d;
}
DINL u64 add2(u64 a, u64 b) {
    u64 d; asm("add.rn.f32x2 %0,%1,%2;" : "=l"(d) : "l"(a), "l"(b)); return d;
}
DINL u64 sub2(u64 a, u64 b) {
    u64 d; asm("sub.rn.f32x2 %0,%1,%2;" : "=l"(d) : "l"(a), "l"(b)); return d;
}
DINL u64 mul2(u64 a, u64 b) {
    u64 d; asm("mul.rn.f32x2 %0,%1,%2;" : "=l"(d) : "l"(a), "l"(b)); return d;
}

constexpr int S_LEN = 4096;
constexpr int H_DIM = 128;
constexpr int K_SZ  = 16;
constexpr int LROWS = 128;            // rows per warp strip
constexpr int PF    = 4;              // prefetch depth
constexpr int ROW_V = H_DIM / 4;      // 32 ulonglong2 per row

__global__ void __launch_bounds__(128, 3) fconv_ln_kernel(
    const float* __restrict__ x,
    const float* __restrict__ cw,
    const float* __restrict__ lnw,
    const float* __restrict__ lnb,
    float* __restrict__ out)
{
    const int lane  = threadIdx.x & 31;
    const int gwarp = (blockIdx.x * blockDim.x + threadIdx.x) >> 5;
    const int spb   = S_LEN / LROWS;          // 32 strips per batch
    const int b     = gwarp / spb;
    const int t0    = (gwarp % spb) * LROWS;  // multiple of 128 (so t0 % 16 == 0)

    const ulonglong2* __restrict__ xb =
        reinterpret_cast<const ulonglong2*>(x) + (size_t)b * S_LEN * ROW_V;
    ulonglong2* __restrict__ ob =
        reinterpret_cast<ulonglong2*>(out) + (size_t)b * S_LEN * ROW_V;

    // ---- weights, pre-scaled by 1/64, as f32x2 pairs: 64 regs ----
    u64 w[K_SZ][2];
    {
        const ulonglong2* cw2 = reinterpret_cast<const ulonglong2*>(cw);
        const u64 sc2 = pack2(0.015625f, 0.015625f);
#pragma unroll
        for (int k = 0; k < K_SZ; k++) {
            ulonglong2 v = cw2[k * ROW_V + lane];
            w[k][0] = mul2(v.x, sc2);
            w[k][1] = mul2(v.y, sc2);
        }
    }

    // ---- LN params for this lane's 4 channels ----
    u64 lw[2], lb[2];
    {
        ulonglong2 v = reinterpret_cast<const ulonglong2*>(lnw)[lane];
        lw[0] = v.x; lw[1] = v.y;
        ulonglong2 u = reinterpret_cast<const ulonglong2*>(lnb)[lane];
        lb[0] = u.x; lb[1] = u.y;
    }

    // ---- forward partial accumulators for outputs t..t+15: 64 regs ----
    u64 acc[K_SZ][2];
#pragma unroll
    for (int i = 0; i < K_SZ; i++) { acc[i][0] = 0ull; acc[i][1] = 0ull; }

    // ---- halo: rows t0-15..t0-1 contribute to outputs >= t0 only ----
    // row r = t0-15+i has r % 16 == i+1; valid k range: 15-i .. 15.
#pragma unroll
    for (int i = 0; i < K_SZ - 1; i++) {
        const int r = (t0 - (K_SZ - 1) + i + S_LEN) & (S_LEN - 1);
        ulonglong2 v = xb[r * ROW_V + lane];
#pragma unroll
        for (int k = K_SZ - 1 - i; k < K_SZ; k++) {
            const int s = (i + 1 + k) & (K_SZ - 1);
            acc[s][0] = fma2(w[k][0], v.x, acc[s][0]);
            acc[s][1] = fma2(w[k][1], v.y, acc[s][1]);
        }
    }

    // ---- prefetch queue: rows t0..t0+3 ----
    ulonglong2 pf[PF];
#pragma unroll
    for (int q = 0; q < PF; q++)
        pf[q] = xb[(t0 + q) * ROW_V + lane];

#pragma unroll 1
    for (int jo = 0; jo < LROWS; jo += K_SZ) {
#pragma unroll
        for (int j = 0; j < K_SZ; j++) {
            const int t = t0 + jo + j;              // t % 16 == j
            ulonglong2 cur = pf[j & (PF - 1)];
            pf[j & (PF - 1)] = xb[((t + PF) & (S_LEN - 1)) * ROW_V + lane];

            // k = 0 completes output row t; residual is cur itself.
            u64 h0 = add2(fma2(w[0][0], cur.x, acc[j][0]), cur.x);
            u64 h1 = add2(fma2(w[0][1], cur.y, acc[j][1]), cur.y);

            // k = 15 overwrites slot (j+15)&15 == slot emitted last iteration
            {
                const int s = (j + 15) & (K_SZ - 1);
                acc[s][0] = mul2(w[15][0], cur.x);
                acc[s][1] = mul2(w[15][1], cur.y);
            }
            // k = 1..14 accumulate forward
#pragma unroll
            for (int k = 1; k < K_SZ - 1; k++) {
                const int s = (j + k) & (K_SZ - 1);
                acc[s][0] = fma2(w[k][0], cur.x, acc[s][0]);
                acc[s][1] = fma2(w[k][1], cur.y, acc[s][1]);
            }

            // ---- LayerNorm over 128 channels (warp owns the full row) ----
            float f0, f1, f2, f3;
            unpack2(h0, f0, f1);
            unpack2(h1, f2, f3);
            float s  = (f0 + f1) + (f2 + f3);
            float sq = fmaf(f0, f0, fmaf(f1, f1, fmaf(f2, f2, f3 * f3)));
#pragma unroll
            for (int off = 16; off > 0; off >>= 1) {
                s  += __shfl_xor_sync(0xffffffffu, s,  off);
                sq += __shfl_xor_sync(0xffffffffu, sq, off);
            }
            const float mean = s * (1.0f / 128.0f);
            float var = fmaf(sq, 1.0f / 128.0f, -mean * mean);
            var = fmaxf(var, 0.0f);
            const float inv = rsqrtf(var + 1e-12f);

            const u64 inv2  = pack2(inv, inv);
            const u64 mean2 = pack2(mean, mean);
            ulonglong2 ov;
            ov.x = fma2(mul2(sub2(h0, mean2), inv2), lw[0], lb[0]);
            ov.y = fma2(mul2(sub2(h1, mean2), inv2), lw[1], lb[1]);
            ob[t * ROW_V + lane] = ov;
        }
    }
}

extern "C" void kernel_launch(void* const* d_in, const int* in_sizes, int n_in,
                              void* d_out, int out_size)
{
    const float* x   = (const float*)d_in[0];  // [64, 4096, 128]
    const float* cw  = (const float*)d_in[1];  // [1, 16, 128]
    const float* lnw = (const float*)d_in[2];  // [128]
    const float* lnb = (const float*)d_in[3];  // [128]
    float* out = (float*)d_out;                // [64, 4096, 128]

    const int total_warps = 64 * (S_LEN / LROWS);   // 2048
    const int blocks = total_warps / 4;             // 512
    fconv_ln_kernel<<<blocks, 128>>>(x, cw, lnw, lnb, out);
}

// round 4
// speedup vs baseline: 1.3493x; 1.3493x over previous
#include <cuda_runtime.h>
#include <cstdint>

// FConvLayer: irfft(rfft(x)*rfft(w_pad)) ortho == circular depthwise conv / 64.
// y[b,t,h] = (1/64) * sum_{k<16} w[k,h] * x[b,(t-k) mod 4096,h]
// out = LayerNorm_H(y + x) * ln_w + ln_b
//
// R4 design: scatter-form register conv + cp.async per-lane SMEM FIFO.
//  - 1 warp = 128-row t-strip; lane l owns h in [4l,4l+4) as two f32x2 pairs.
//  - 16 forward partial accumulators (scatter): input row t adds w[k]*x[t]
//    to acc[(t+k)&15]; output t completes when row t is consumed.
//  - x rows stream through a 16-slot per-warp SMEM ring via cp.async.cg 16B
//    per lane (1 LDGSTS + 1 commit per row). Each lane reads back only its
//    own 16B -> no barriers needed, MLP decoupled from register file.
//  - 96KB of reads in flight per SM (16 slots x 512B x 12 warps).

typedef unsigned long long u64;
#define DINL __device__ __forceinline__

DINL u64 pack2(float lo, float hi) {
    u64 r; asm("mov.b64 %0, {%1,%2};" : "=l"(r) : "f"(lo), "f"(hi)); return r;
}
DINL void unpack2(u64 v, float& lo, float& hi) {
    asm("mov.b64 {%0,%1}, %2;" : "=f"(lo), "=f"(hi) : "l"(v));
}
DINL u64 fma2(u64 a, u64 b, u64 c) {
    u64 d; asm("fma.rn.f32x2 %0,%1,%2,%3;" : "=l"(d) : "l"(a), "l"(b), "l"(c)); return d;
}
DINL u64 add2(u64 a, u64 b) {
    u64 d; asm("add.rn.f32x2 %0,%1,%2;" : "=l"(d) : "l"(a), "l"(b)); return d;
}
DINL u64 sub2(u64 a, u64 b) {
    u64 d; asm("sub.rn.f32x2 %0,%1,%2;" : "=l"(d) : "l"(a), "l"(b)); return d;
}
DINL u64 mul2(u64 a, u64 b) {
    u64 d; asm("mul.rn.f32x2 %0,%1,%2;" : "=l"(d) : "l"(a), "l"(b)); return d;
}

#define CP16(smem_u32, gptr) \
    asm volatile("cp.async.cg.shared.global [%0], [%1], 16;" \
                 :: "r"(smem_u32), "l"(gptr) : "memory")
#define CP_COMMIT() asm volatile("cp.async.commit_group;" ::: "memory")
#define CP_WAIT(n)  asm volatile("cp.async.wait_group %0;" :: "n"(n) : "memory")

constexpr int S_LEN = 4096;
constexpr int H_DIM = 128;
constexpr int K_SZ  = 16;
constexpr int LROWS = 128;            // rows per warp strip
constexpr int DEPTH = 16;             // SMEM ring slots per warp (== K_SZ)
constexpr int ROW_B = H_DIM * 4;      // 512 bytes per row
constexpr int ROW_V = H_DIM / 4;      // 32 ulonglong2 per row

__global__ void __launch_bounds__(128, 3) fconv_ln_kernel(
    const float* __restrict__ x,
    const float* __restrict__ cw,
    const float* __restrict__ lnw,
    const float* __restrict__ lnb,
    float* __restrict__ out)
{
    __shared__ __align__(16) unsigned char ring[4 * DEPTH * ROW_B];  // 32KB

    const int lane  = threadIdx.x & 31;
    const int warp  = threadIdx.x >> 5;
    const int gwarp = (blockIdx.x * blockDim.x + threadIdx.x) >> 5;
    const int spb   = S_LEN / LROWS;          // 32 strips per batch
    const int b     = gwarp / spb;
    const int t0    = (gwarp % spb) * LROWS;  // multiple of 128

    const char* __restrict__ xb =
        reinterpret_cast<const char*>(x) + (size_t)b * S_LEN * ROW_B;
    ulonglong2* __restrict__ ob =
        reinterpret_cast<ulonglong2*>(out) + (size_t)b * S_LEN * ROW_V;

    // per-lane SMEM FIFO base (byte offset of this lane's 16B in slot 0)
    unsigned char* const ring_c = ring + warp * (DEPTH * ROW_B) + lane * 16;
    const uint32_t ring_s =
        (uint32_t)__cvta_generic_to_shared(ring_c);

    // ---- weights, pre-scaled by 1/64, as f32x2 pairs: 64 regs ----
    u64 w[K_SZ][2];
    {
        const ulonglong2* cw2 = reinterpret_cast<const ulonglong2*>(cw);
        const u64 sc2 = pack2(0.015625f, 0.015625f);
#pragma unroll
        for (int k = 0; k < K_SZ; k++) {
            ulonglong2 v = cw2[k * ROW_V + lane];
            w[k][0] = mul2(v.x, sc2);
            w[k][1] = mul2(v.y, sc2);
        }
    }

    // ---- LN params for this lane's 4 channels ----
    u64 lw[2], lb[2];
    {
        ulonglong2 v = reinterpret_cast<const ulonglong2*>(lnw)[lane];
        lw[0] = v.x; lw[1] = v.y;
        ulonglong2 u = reinterpret_cast<const ulonglong2*>(lnb)[lane];
        lb[0] = u.x; lb[1] = u.y;
    }

    // ---- kick off the FIFO: rows t0..t0+15 into slots 0..15 ----
#pragma unroll
    for (int q = 0; q < DEPTH; q++) {
        CP16(ring_s + q * ROW_B, xb + (size_t)(t0 + q) * ROW_B + lane * 16);
        CP_COMMIT();
    }

    // ---- forward partial accumulators: 64 regs ----
    u64 acc[K_SZ][2];
#pragma unroll
    for (int i = 0; i < K_SZ; i++) { acc[i][0] = 0ull; acc[i][1] = 0ull; }

    // ---- halo: rows t0-15..t0-1 (plain LDG; one-time) ----
    // row r = t0-15+i has r % 16 == i+1; valid k range: 15-i .. 15.
    const ulonglong2* xb2 = reinterpret_cast<const ulonglong2*>(xb);
#pragma unroll
    for (int i = 0; i < K_SZ - 1; i++) {
        const int r = (t0 - (K_SZ - 1) + i + S_LEN) & (S_LEN - 1);
        ulonglong2 v = xb2[r * ROW_V + lane];
#pragma unroll
        for (int k = K_SZ - 1 - i; k < K_SZ; k++) {
            const int s = (i + 1 + k) & (K_SZ - 1);
            acc[s][0] = fma2(w[k][0], v.x, acc[s][0]);
            acc[s][1] = fma2(w[k][1], v.y, acc[s][1]);
        }
    }

#pragma unroll 1
    for (int jo = 0; jo < LROWS; jo += K_SZ) {
#pragma unroll
        for (int j = 0; j < K_SZ; j++) {
            const int t = t0 + jo + j;              // t % 16 == j, slot == j

            // wait until row t's copy has landed (<= DEPTH-1 groups pending)
            CP_WAIT(DEPTH - 1);
            ulonglong2 cur =
                *reinterpret_cast<const ulonglong2*>(ring_c + j * ROW_B);

            // refill slot j with row t+16 (skip past strip end); always commit
            if (jo + j + DEPTH < LROWS) {
                CP16(ring_s + j * ROW_B,
                     xb + (size_t)(t + DEPTH) * ROW_B + lane * 16);
            }
            CP_COMMIT();

            // k = 0 completes output row t; residual is cur itself.
            u64 h0 = add2(fma2(w[0][0], cur.x, acc[j][0]), cur.x);
            u64 h1 = add2(fma2(w[0][1], cur.y, acc[j][1]), cur.y);

            // k = 15 overwrites the slot emitted last iteration
            {
                const int s = (j + 15) & (K_SZ - 1);
                acc[s][0] = mul2(w[15][0], cur.x);
                acc[s][1] = mul2(w[15][1], cur.y);
            }
            // k = 1..14 accumulate forward
#pragma unroll
            for (int k = 1; k < K_SZ - 1; k++) {
                const int s = (j + k) & (K_SZ - 1);
                acc[s][0] = fma2(w[k][0], cur.x, acc[s][0]);
                acc[s][1] = fma2(w[k][1], cur.y, acc[s][1]);
            }

            // ---- LayerNorm over 128 channels (warp owns the full row) ----
            float f0, f1, f2, f3;
            unpack2(h0, f0, f1);
            unpack2(h1, f2, f3);
            float s  = (f0 + f1) + (f2 + f3);
            float sq = fmaf(f0, f0, fmaf(f1, f1, fmaf(f2, f2, f3 * f3)));
#pragma unroll
            for (int off = 16; off > 0; off >>= 1) {
                s  += __shfl_xor_sync(0xffffffffu, s,  off);
                sq += __shfl_xor_sync(0xffffffffu, sq, off);
            }
            const float mean = s * (1.0f / 128.0f);
            float var = fmaf(sq, 1.0f / 128.0f, -mean * mean);
            var = fmaxf(var, 0.0f);
            const float inv = rsqrtf(var + 1e-12f);

            const u64 inv2  = pack2(inv, inv);
            const u64 mean2 = pack2(mean, mean);
            ulonglong2 ov;
            ov.x = fma2(mul2(sub2(h0, mean2), inv2), lw[0], lb[0]);
            ov.y = fma2(mul2(sub2(h1, mean2), inv2), lw[1], lb[1]);
            ob[t * ROW_V + lane] = ov;
        }
    }
}

extern "C" void kernel_launch(void* const* d_in, const int* in_sizes, int n_in,
                              void* d_out, int out_size)
{
    const float* x   = (const float*)d_in[0];  // [64, 4096, 128]
    const float* cw  = (const float*)d_in[1];  // [1, 16, 128]
    const float* lnw = (const float*)d_in[2];  // [128]
    const float* lnb = (const float*)d_in[3];  // [128]
    float* out = (float*)d_out;                // [64, 4096, 128]

    const int total_warps = 64 * (S_LEN / LROWS);   // 2048
    const int blocks = total_warps / 4;             // 512
    fconv_ln_kernel<<<blocks, 128>>>(x, cw, lnw, lnb, out);
}

// round 7
// speedup vs baseline: 1.5515x; 1.1499x over previous
#include <cuda_runtime.h>
#include <cstdint>

// FConvLayer: irfft(rfft(x)*rfft(w_pad)) ortho == circular depthwise conv / 64.
// y[b,t,h] = (1/64) * sum_{k<16} w[k,h] * x[b,(t-k) mod 4096,h]
// out = LayerNorm_H(y + x) * ln_w + ln_b
//
// R6: scatter-form register conv + cp.async per-lane SMEM FIFO
//     + packed-f32x2 SHFL butterfly + 2-deep software pipeline.
//  - 1 warp = 128-row t-strip; lane l owns h in [4l,4l+4) (two f32x2 pairs).
//  - 16 forward partial accumulators; row t completes as it is consumed.
//  - (sum, sumsq) packed in ONE u64; butterfly = 10 SHFL + 5 add2.
//  - Row t's butterfly/normalize/store deferred one iteration so the SHFL
//    chain interleaves with row t+1's independent conv fma2 stream.

typedef unsigned long long u64;
#define DINL __device__ __forceinline__

DINL u64 pack2(float lo, float hi) {
    u64 r; asm("mov.b64 %0, {%1,%2};" : "=l"(r) : "f"(lo), "f"(hi)); return r;
}
DINL void unpack2(u64 v, float& lo, float& hi) {
    asm("mov.b64 {%0,%1}, %2;" : "=f"(lo), "=f"(hi) : "l"(v));
}
DINL u64 fma2(u64 a, u64 b, u64 c) {
    u64 d; asm("fma.rn.f32x2 %0,%1,%2,%3;" : "=l"(d) : "l"(a), "l"(b), "l"(c)); return d;
}
DINL u64 add2(u64 a, u64 b) {
    u64 d; asm("add.rn.f32x2 %0,%1,%2;" : "=l"(d) : "l"(a), "l"(b)); return d;
}
DINL u64 sub2(u64 a, u64 b) {
    u64 d; asm("sub.rn.f32x2 %0,%1,%2;" : "=l"(d) : "l"(a), "l"(b)); return d;
}
DINL u64 mul2(u64 a, u64 b) {
    u64 d; asm("mul.rn.f32x2 %0,%1,%2;" : "=l"(d) : "l"(a), "l"(b)); return d;
}
DINL void stcs2(void* p, u64 a, u64 b) {
    asm volatile("st.global.cs.v2.b64 [%0], {%1,%2};"
                 :: "l"(p), "l"(a), "l"(b) : "memory");
}

#define CP16(smem_u32, gptr) \
    asm volatile("cp.async.cg.shared.global [%0], [%1], 16;" \
                 :: "r"(smem_u32), "l"(gptr) : "memory")
#define CP_COMMIT() asm volatile("cp.async.commit_group;" ::: "memory")
#define CP_WAIT(n)  asm volatile("cp.async.wait_group %0;" :: "n"(n) : "memory")

constexpr int S_LEN = 4096;
constexpr int H_DIM = 128;
constexpr int K_SZ  = 16;
constexpr int LROWS = 128;            // rows per warp strip
constexpr int DEPTH = 16;             // SMEM ring slots per warp
constexpr int ROW_B = H_DIM * 4;      // 512 bytes per row
constexpr int ROW_V = H_DIM / 4;      // 32 ulonglong2 per row

// Finish the previous row: butterfly its packed partials, normalize, store.
#define FINISH_PREV()                                                         \
    do {                                                                      \
        u64 tot = psp;                                                        \
        _Pragma("unroll")                                                     \
        for (int off = 16; off > 0; off >>= 1)                                \
            tot = add2(tot, __shfl_xor_sync(0xffffffffu, tot, off));          \
        float s_, sq_;                                                        \
        unpack2(tot, s_, sq_);                                                \
        const float mean = s_ * (1.0f / 128.0f);                              \
        float var = fmaf(sq_, 1.0f / 128.0f, -mean * mean);                   \
        var = fmaxf(var, 0.0f);                                               \
        const float inv = rsqrtf(var + 1e-12f);                               \
        const u64 inv2  = pack2(inv, inv);                                    \
        const u64 mean2 = pack2(mean, mean);                                  \
        u64 o0 = fma2(mul2(sub2(hp0, mean2), inv2), lw[0], lb[0]);            \
        u64 o1 = fma2(mul2(sub2(hp1, mean2), inv2), lw[1], lb[1]);            \
        stcs2(ob + (size_t)tp * ROW_V + lane, o0, o1);                        \
    } while (0)

// One row: conv + local partial sums; then complete the PREVIOUS row so its
// SHFL chain overlaps this row's independent fma2 stream.
#define ROW_BODY(JJ, FIN)                                                     \
    do {                                                                      \
        const int t_ = t0 + jo + (JJ);                                        \
        CP_WAIT(DEPTH - 1);                                                   \
        ulonglong2 cur =                                                      \
            *reinterpret_cast<const ulonglong2*>(ring_c + (JJ) * ROW_B);      \
        if (jo + (JJ) + DEPTH < LROWS) {                                      \
            CP16(ring_s + (JJ) * ROW_B,                                       \
                 xb + (size_t)(t_ + DEPTH) * ROW_B + lane * 16);              \
        }                                                                     \
        CP_COMMIT();                                                          \
        u64 h0 = add2(fma2(w[0][0], cur.x, acc[(JJ)][0]), cur.x);             \
        u64 h1 = add2(fma2(w[0][1], cur.y, acc[(JJ)][1]), cur.y);             \
        {                                                                     \
            const int s15_ = ((JJ) + 15) & (K_SZ - 1);                        \
            acc[s15_][0] = mul2(w[15][0], cur.x);                             \
            acc[s15_][1] = mul2(w[15][1], cur.y);                             \
        }                                                                     \
        _Pragma("unroll")                                                     \
        for (int k = 1; k < K_SZ - 1; k++) {                                  \
            const int s_ = ((JJ) + k) & (K_SZ - 1);                           \
            acc[s_][0] = fma2(w[k][0], cur.x, acc[s_][0]);                    \
            acc[s_][1] = fma2(w[k][1], cur.y, acc[s_][1]);                    \
        }                                                                     \
        float f0, f1, f2, f3;                                                 \
        unpack2(h0, f0, f1);                                                  \
        unpack2(h1, f2, f3);                                                  \
        u64 ps = pack2((f0 + f1) + (f2 + f3),                                 \
                       fmaf(f0, f0, fmaf(f1, f1, fmaf(f2, f2, f3 * f3))));    \
        if (FIN) { FINISH_PREV(); }                                           \
        hp0 = h0; hp1 = h1; psp = ps; tp = t_;                                \
    } while (0)

__global__ void __launch_bounds__(128, 3) fconv_ln_kernel(
    const float* __restrict__ x,
    const float* __restrict__ cw,
    const float* __restrict__ lnw,
    const float* __restrict__ lnb,
    float* __restrict__ out)
{
    __shared__ __align__(16) unsigned char ring[4 * DEPTH * ROW_B];  // 32KB

    const int lane  = threadIdx.x & 31;
    const int warp  = threadIdx.x >> 5;
    const int gwarp = (blockIdx.x * blockDim.x + threadIdx.x) >> 5;
    const int spb   = S_LEN / LROWS;          // 32 strips per batch
    const int b     = gwarp / spb;
    const int t0    = (gwarp % spb) * LROWS;  // multiple of 128

    const char* __restrict__ xb =
        reinterpret_cast<const char*>(x) + (size_t)b * S_LEN * ROW_B;
    ulonglong2* __restrict__ ob =
        reinterpret_cast<ulonglong2*>(out) + (size_t)b * S_LEN * ROW_V;

    unsigned char* const ring_c = ring + warp * (DEPTH * ROW_B) + lane * 16;
    const uint32_t ring_s = (uint32_t)__cvta_generic_to_shared(ring_c);

    // ---- weights, pre-scaled by 1/64, as f32x2 pairs ----
    u64 w[K_SZ][2];
    {
        const ulonglong2* cw2 = reinterpret_cast<const ulonglong2*>(cw);
        const u64 sc2 = pack2(0.015625f, 0.015625f);
#pragma unroll
        for (int k = 0; k < K_SZ; k++) {
            ulonglong2 v = cw2[k * ROW_V + lane];
            w[k][0] = mul2(v.x, sc2);
            w[k][1] = mul2(v.y, sc2);
        }
    }

    // ---- LN params ----
    u64 lw[2], lb[2];
    {
        ulonglong2 v = reinterpret_cast<const ulonglong2*>(lnw)[lane];
        lw[0] = v.x; lw[1] = v.y;
        ulonglong2 u = reinterpret_cast<const ulonglong2*>(lnb)[lane];
        lb[0] = u.x; lb[1] = u.y;
    }

    // ---- kick off the FIFO: rows t0..t0+15 into slots 0..15 ----
#pragma unroll
    for (int q = 0; q < DEPTH; q++) {
        CP16(ring_s + q * ROW_B, xb + (size_t)(t0 + q) * ROW_B + lane * 16);
        CP_COMMIT();
    }

    // ---- forward partial accumulators ----
    u64 acc[K_SZ][2];
#pragma unroll
    for (int i = 0; i < K_SZ; i++) { acc[i][0] = 0ull; acc[i][1] = 0ull; }

    // ---- halo: rows t0-15..t0-1 (one-time LDG) ----
    const ulonglong2* xb2 = reinterpret_cast<const ulonglong2*>(xb);
#pragma unroll
    for (int i = 0; i < K_SZ - 1; i++) {
        const int r = (t0 - (K_SZ - 1) + i + S_LEN) & (S_LEN - 1);
        ulonglong2 v = xb2[r * ROW_V + lane];
#pragma unroll
        for (int k = K_SZ - 1 - i; k < K_SZ; k++) {
            const int s = (i + 1 + k) & (K_SZ - 1);
            acc[s][0] = fma2(w[k][0], v.x, acc[s][0]);
            acc[s][1] = fma2(w[k][1], v.y, acc[s][1]);
        }
    }

    // ---- pipelined state for the deferred row ----
    u64 hp0 = 0ull, hp1 = 0ull, psp = 0ull;
    int tp = t0;

    // ---- peel first block of 16 rows: row 0 has no predecessor ----
    {
        const int jo = 0;
#pragma unroll
        for (int j = 0; j < K_SZ; j++) {
            if (j == 0) { ROW_BODY(j, false); }
            else        { ROW_BODY(j, true);  }
        }
    }
#pragma unroll 1
    for (int jo = K_SZ; jo < LROWS; jo += K_SZ) {
#pragma unroll
        for (int j = 0; j < K_SZ; j++) {
            ROW_BODY(j, true);
        }
    }

    // ---- epilogue: finish the final row ----
    FINISH_PREV();
}

extern "C" void kernel_launch(void* const* d_in, const int* in_sizes, int n_in,
                              void* d_out, int out_size)
{
    const float* x   = (const float*)d_in[0];  // [64, 4096, 128]
    const float* cw  = (const float*)d_in[1];  // [1, 16, 128]
    const float* lnw = (const float*)d_in[2];  // [128]
    const float* lnb = (const float*)d_in[3];  // [128]
    float* out = (float*)d_out;                // [64, 4096, 128]

    const int total_warps = 64 * (S_LEN / LROWS);   // 2048
    const int blocks = total_warps / 4;             // 512
    fconv_ln_kernel<<<blocks, 128>>>(x, cw, lnw, lnb, out);
}